// round 6
// baseline (speedup 1.0000x reference)
#include <cuda_runtime.h>
#include <cstdint>
#include <cuda_fp16.h>

// ============================================================================
// out[b,n] = sum_k x[b,k] * W[k,n]
//   x: [512, 2^20] f32, W: [2^20, 128] f32, out: [512,128] f32
// R4 design:
//   K1: prepass W -> Wp pair-packed fp16 (u32 = {half k=2j, half k=2j+1})
//   K2: GEMM, MTILE=128/KTILE=32, split-K 74 (grid 296 = 148 SMs x occ 2).
//       A: LDG f32 -> reg -> F2FP pack -> STS fp16 (no f32 smem staging)
//       B: cp.async fp16 direct from Wp into triple-buffered smem
//       mma.sync.m16n8k16.f16 with f32 accumulators
//   K3: reduce split-K partials with 4-way MLP
// ============================================================================

static constexpr int M_TOTAL = 512;
static constexpr int N_DIM   = 128;
static constexpr int K_TOTAL = 1 << 20;

static constexpr int MTILE   = 128;
static constexpr int KTILE   = 32;
static constexpr int NUM_MT  = M_TOTAL / MTILE;    // 4
static constexpr int KSPLITS = 74;                 // 296 CTAs = one wave @ occ 2
static constexpr int NTILES_K = K_TOTAL / KTILE;   // 32768
static constexpr int BASE_T  = NTILES_K / KSPLITS; // 442
static constexpr int REM_T   = NTILES_K - BASE_T * KSPLITS; // 60

// smem (u32 units)
static constexpr int AH_PITCH = 20;                   // 16 data u32 + 4 pad
static constexpr int AH_WORDS = MTILE * AH_PITCH;     // 2560
static constexpr int BH_PITCH = 132;                  // 128 data u32 + 4 pad
static constexpr int BH_SLOT  = (KTILE / 2) * BH_PITCH; // 2112
static constexpr int SMEM_WORDS = AH_WORDS + 3 * BH_SLOT; // 8896 u32 = 35584 B

// device scratch
__device__ uint32_t g_Wp[(size_t)(K_TOTAL / 2) * N_DIM];           // 256 MiB
__device__ float g_part[(size_t)KSPLITS * NUM_MT * MTILE * N_DIM]; // 19.4 MiB

// ---------------------------------------------------------------------------
__device__ __forceinline__ uint32_t smem_to_u32(const void* p) {
    uint32_t a;
    asm("{ .reg .u64 t; cvta.to.shared.u64 t, %1; cvt.u32.u64 %0, t; }" : "=r"(a) : "l"(p));
    return a;
}
__device__ __forceinline__ void cp_async16(uint32_t dst, const void* src) {
    asm volatile("cp.async.cg.shared.global [%0], [%1], 16;" :: "r"(dst), "l"(src));
}
__device__ __forceinline__ void cp_commit() {
    asm volatile("cp.async.commit_group;" ::: "memory");
}
template <int N>
__device__ __forceinline__ void cp_wait() {
    asm volatile("cp.async.wait_group %0;" :: "n"(N) : "memory");
}
__device__ __forceinline__ uint32_t pack_h2(float lo, float hi) {
    __half2 h = __floats2half2_rn(lo, hi);   // .x = lo (low 16 bits)
    return *reinterpret_cast<uint32_t*>(&h);
}
__device__ __forceinline__ void mma_f16(float* d, const uint32_t* a, const uint32_t* b) {
    asm volatile(
        "mma.sync.aligned.m16n8k16.row.col.f32.f16.f16.f32 "
        "{%0,%1,%2,%3}, {%4,%5,%6,%7}, {%8,%9}, {%0,%1,%2,%3};"
        : "+f"(d[0]), "+f"(d[1]), "+f"(d[2]), "+f"(d[3])
        : "r"(a[0]), "r"(a[1]), "r"(a[2]), "r"(a[3]), "r"(b[0]), "r"(b[1]));
}

// ---------------------------------------------------------------------------
// K1: W [2^20,128] f32 -> Wp [2^19][128] u32, Wp[k2][n] = {W[2k2][n], W[2k2+1][n]}
// ---------------------------------------------------------------------------
__global__ void __launch_bounds__(256) pack_w_kernel(const float* __restrict__ W,
                                                     uint32_t* __restrict__ Wp) {
    size_t idx = (size_t)blockIdx.x * 256 + threadIdx.x;  // uint4 index, 2^24 total
    size_t k2 = idx >> 5;
    int nq = (int)(idx & 31);
    const float4* W4 = reinterpret_cast<const float4*>(W);
    float4 lo = W4[(2 * k2) * 32 + nq];
    float4 hi = W4[(2 * k2 + 1) * 32 + nq];
    uint4 o;
    o.x = pack_h2(lo.x, hi.x);
    o.y = pack_h2(lo.y, hi.y);
    o.z = pack_h2(lo.z, hi.z);
    o.w = pack_h2(lo.w, hi.w);
    reinterpret_cast<uint4*>(Wp)[idx] = o;
}

// ---------------------------------------------------------------------------
// K2: GEMM. grid 296 (mt = bid&3, ks = bid>>2), 256 threads, warps 2(m) x 4(n).
// ---------------------------------------------------------------------------
__global__ void __launch_bounds__(256, 2) gemm_kernel(
    const float* __restrict__ x, const uint32_t* __restrict__ Wp,
    float* __restrict__ partials) {
    __shared__ uint32_t smem[SMEM_WORDS];
    uint32_t* const sAh = smem;                 // [128][20]
    uint32_t* const sBh = smem + AH_WORDS;      // 3 x [16][132]
    const uint32_t sBh_base = smem_to_u32(sBh);

    const int tid  = threadIdx.x;
    const int wid  = tid >> 5;
    const int lane = tid & 31;
    const int g = lane >> 2;
    const int c = lane & 3;
    const int m_off = (wid >> 2) * 64;   // 2 m-warps
    const int n_off = (wid & 3) * 32;    // 4 n-warps

    const int mt = blockIdx.x & (NUM_MT - 1);
    const int ks = blockIdx.x >> 2;
    const size_t m_base = (size_t)mt * MTILE;
    const int nt = BASE_T + (ks < REM_T ? 1 : 0);
    const long t0 = (long)ks * BASE_T + (ks < REM_T ? ks : REM_T);

    // A: one row per thread, halfk selects which 16-float half of the k-tile.
    const int a_row   = tid & 127;
    const int a_halfk = tid >> 7;
    const float* a_src_base = x + (m_base + a_row) * (size_t)K_TOTAL + a_halfk * 16;
    uint32_t* const a_dst = sAh + a_row * AH_PITCH + a_halfk * 8;

    // B staging: 2 x 16B chunks per thread per stage
    const int b_kr0 = tid >> 5,         b_nq0 = tid & 31;
    const int b_kr1 = (tid + 256) >> 5, b_nq1 = (tid + 256) & 31;

    auto copy_B = [&](int slot, int tile) {
        const size_t k2b = (size_t)(t0 + tile) * (KTILE / 2);
        const uint32_t dst = sBh_base + slot * (BH_SLOT * 4);
        cp_async16(dst + b_kr0 * (BH_PITCH * 4) + b_nq0 * 16,
                   Wp + ((k2b + b_kr0) << 7) + b_nq0 * 4);
        cp_async16(dst + b_kr1 * (BH_PITCH * 4) + b_nq1 * 16,
                   Wp + ((k2b + b_kr1) << 7) + b_nq1 * 4);
        cp_commit();
    };

    float4 f[4];   // A prefetch registers (one stage)
    auto ld_A = [&](int tile) {
        const float4* p = reinterpret_cast<const float4*>(
            a_src_base + (size_t)(t0 + tile) * KTILE);
#pragma unroll
        for (int i = 0; i < 4; i++) f[i] = p[i];
    };

    float acc[4][4][4];
#pragma unroll
    for (int mi = 0; mi < 4; mi++)
#pragma unroll
        for (int ni = 0; ni < 4; ni++)
#pragma unroll
            for (int r = 0; r < 4; r++) acc[mi][ni][r] = 0.0f;

    // prologue
    copy_B(0, 0);
    copy_B(1, 1);
    ld_A(0);

    int bslot = 0, wslot = 2;   // read slot for stage it; write slot for it+2
    for (int it = 0; it < nt; it++) {
        cp_wait<1>();   // B(it) landed (<=1 outstanding group = B(it+1))

        // pack A(it) from registers -> Ah (conflict-free STS.128: groups 5r mod 8)
        {
            uint4 o1, o2;
            o1.x = pack_h2(f[0].x, f[0].y); o1.y = pack_h2(f[0].z, f[0].w);
            o1.z = pack_h2(f[1].x, f[1].y); o1.w = pack_h2(f[1].z, f[1].w);
            o2.x = pack_h2(f[2].x, f[2].y); o2.y = pack_h2(f[2].z, f[2].w);
            o2.z = pack_h2(f[3].x, f[3].y); o2.w = pack_h2(f[3].z, f[3].w);
            *reinterpret_cast<uint4*>(a_dst)     = o1;
            *reinterpret_cast<uint4*>(a_dst + 4) = o2;
        }
        if (it + 1 < nt) ld_A(it + 1);              // A prefetch (distance 1)
        if (it + 2 < nt) copy_B(wslot, it + 2);     // B prefetch (distance 2)
        else cp_commit();                           // uniform group accounting

        __syncthreads();   // Ah + Bh[bslot] visible to all warps

        const uint32_t* Bhp = sBh + bslot * BH_SLOT;
#pragma unroll
        for (int kk = 0; kk < 2; kk++) {
            uint32_t a[4][4], b[4][2];
#pragma unroll
            for (int mi = 0; mi < 4; mi++) {
                const int r0 = m_off + mi * 16 + g;
                const uint32_t* A0 = sAh + r0 * AH_PITCH + kk * 8;
                const uint32_t* A1 = sAh + (r0 + 8) * AH_PITCH + kk * 8;
                a[mi][0] = A0[c];
                a[mi][1] = A1[c];
                a[mi][2] = A0[c + 4];
                a[mi][3] = A1[c + 4];
            }
#pragma unroll
            for (int ni = 0; ni < 4; ni++) {
                const int col = n_off + ni * 8 + g;
                b[ni][0] = Bhp[(kk * 8 + c) * BH_PITCH + col];
                b[ni][1] = Bhp[(kk * 8 + c + 4) * BH_PITCH + col];
            }
#pragma unroll
            for (int mi = 0; mi < 4; mi++)
#pragma unroll
                for (int ni = 0; ni < 4; ni++)
                    mma_f16(acc[mi][ni], a[mi], b[ni]);
        }
        __syncthreads();   // reads of Ah / Bh[bslot] done before overwrite

        if (++bslot == 3) bslot = 0;
        if (++wslot == 3) wslot = 0;
    }

    // epilogue: 128x128 partial
    float* pt = partials + (size_t)blockIdx.x * (MTILE * N_DIM);
#pragma unroll
    for (int mi = 0; mi < 4; mi++) {
        int r0 = m_off + mi * 16 + g;
#pragma unroll
        for (int ni = 0; ni < 4; ni++) {
            int col = n_off + ni * 8 + 2 * c;
            float2 lo = make_float2(acc[mi][ni][0], acc[mi][ni][1]);
            float2 hi = make_float2(acc[mi][ni][2], acc[mi][ni][3]);
            *reinterpret_cast<float2*>(pt + (size_t)r0 * N_DIM + col) = lo;
            *reinterpret_cast<float2*>(pt + (size_t)(r0 + 8) * N_DIM + col) = hi;
        }
    }
}

// ---------------------------------------------------------------------------
// K3: reduce 74 partials -> out, 4-way MLP
// ---------------------------------------------------------------------------
__global__ void __launch_bounds__(256) reduce_kernel(const float* __restrict__ pt,
                                                     float* __restrict__ out) {
    int t = blockIdx.x * blockDim.x + threadIdx.x;
    int n  = t & (N_DIM - 1);
    int m  = (t >> 7) & (MTILE - 1);
    int mt = t >> 14;
    const size_t off = (size_t)m * N_DIM + n;
    const size_t mtoff = (size_t)mt * (MTILE * N_DIM);
    const size_t stride = (size_t)NUM_MT * (MTILE * N_DIM);
    float s0 = 0.f, s1 = 0.f, s2 = 0.f, s3 = 0.f;
    int ks = 0;
#pragma unroll 4
    for (; ks + 4 <= KSPLITS; ks += 4) {
        s0 += pt[(size_t)ks * stride + mtoff + off];
        s1 += pt[(size_t)(ks + 1) * stride + mtoff + off];
        s2 += pt[(size_t)(ks + 2) * stride + mtoff + off];
        s3 += pt[(size_t)(ks + 3) * stride + mtoff + off];
    }
    for (; ks < KSPLITS; ks++) s0 += pt[(size_t)ks * stride + mtoff + off];
    out[(size_t)(mt * MTILE + m) * N_DIM + n] = (s0 + s1) + (s2 + s3);
}

// ---------------------------------------------------------------------------
extern "C" void kernel_launch(void* const* d_in, const int* in_sizes, int n_in,
                              void* d_out, int out_size) {
    const float* x = (const float*)d_in[0];
    const float* W = (const float*)d_in[1];
    float* out = (float*)d_out;

    uint32_t* Wp = nullptr;
    float* part = nullptr;
    cudaGetSymbolAddress((void**)&Wp, g_Wp);
    cudaGetSymbolAddress((void**)&part, g_part);

    pack_w_kernel<<<(K_TOTAL / 2) * (N_DIM / 4) / 256, 256>>>(W, Wp);
    gemm_kernel<<<NUM_MT * KSPLITS, 256>>>(x, Wp, part);
    reduce_kernel<<<(M_TOTAL * N_DIM) / 256, 256>>>(part, out);
}

// round 7
// speedup vs baseline: 3.2117x; 3.2117x over previous
#include <cuda_runtime.h>
#include <cstdint>
#include <cuda_fp16.h>

// ============================================================================
// out[b,n] = sum_k x[b,k] * W[k,n]
//   x: [512, 2^20] f32, W: [2^20, 128] f32, out: [512,128] f32
// R5 design:
//   K1: prepass W -> Wp pair-packed fp16 (u32 = {half k=2j, half k=2j+1})
//   K2: GEMM, MTILE=128/KTILE=32, split-K 74 (grid 296 = 148 SMs x occ 2).
//       A: coalesced LDG f32 (8 lanes/row) -> reg pack -> STS.64 fp16,
//          double-buffered; B: cp.async fp16 from Wp, 4-slot ring;
//          ONE __syncthreads per stage; mma.sync.m16n8k16.f16, f32 accum.
//   K3: reduce split-K partials
// ============================================================================

static constexpr int M_TOTAL = 512;
static constexpr int N_DIM   = 128;
static constexpr int K_TOTAL = 1 << 20;

static constexpr int MTILE   = 128;
static constexpr int KTILE   = 32;
static constexpr int NUM_MT  = M_TOTAL / MTILE;    // 4
static constexpr int KSPLITS = 74;                 // 296 CTAs = one wave @ occ 2
static constexpr int NTILES_K = K_TOTAL / KTILE;   // 32768
static constexpr int BASE_T  = NTILES_K / KSPLITS; // 442
static constexpr int REM_T   = NTILES_K - BASE_T * KSPLITS; // 60

// smem (u32 units)
static constexpr int AH_PITCH = 20;                     // 16 data u32 + 4 pad
static constexpr int AH_WORDS = MTILE * AH_PITCH;       // 2560 (one buffer)
static constexpr int BH_PITCH = 136;                    // 128 data + 8 pad -> 8c+g banks
static constexpr int BH_SLOT  = (KTILE / 2) * BH_PITCH; // 2176
static constexpr int SMEM_WORDS = 2 * AH_WORDS + 4 * BH_SLOT; // 13824
static constexpr int SMEM_BYTES = SMEM_WORDS * 4;             // 55296

// device scratch
__device__ uint32_t g_Wp[(size_t)(K_TOTAL / 2) * N_DIM];           // 256 MiB
__device__ float g_part[(size_t)KSPLITS * NUM_MT * MTILE * N_DIM]; // 19.4 MiB

// ---------------------------------------------------------------------------
__device__ __forceinline__ uint32_t smem_to_u32(const void* p) {
    uint32_t a;
    asm("{ .reg .u64 t; cvta.to.shared.u64 t, %1; cvt.u32.u64 %0, t; }" : "=r"(a) : "l"(p));
    return a;
}
__device__ __forceinline__ void cp_async16(uint32_t dst, const void* src) {
    asm volatile("cp.async.cg.shared.global [%0], [%1], 16;" :: "r"(dst), "l"(src));
}
__device__ __forceinline__ void cp_commit() {
    asm volatile("cp.async.commit_group;" ::: "memory");
}
template <int N>
__device__ __forceinline__ void cp_wait() {
    asm volatile("cp.async.wait_group %0;" :: "n"(N) : "memory");
}
__device__ __forceinline__ uint32_t pack_h2(float lo, float hi) {
    __half2 h = __floats2half2_rn(lo, hi);   // .x = lo (low 16 bits)
    return *reinterpret_cast<uint32_t*>(&h);
}
__device__ __forceinline__ void mma_f16(float* d, const uint32_t* a, const uint32_t* b) {
    asm volatile(
        "mma.sync.aligned.m16n8k16.row.col.f32.f16.f16.f32 "
        "{%0,%1,%2,%3}, {%4,%5,%6,%7}, {%8,%9}, {%0,%1,%2,%3};"
        : "+f"(d[0]), "+f"(d[1]), "+f"(d[2]), "+f"(d[3])
        : "r"(a[0]), "r"(a[1]), "r"(a[2]), "r"(a[3]), "r"(b[0]), "r"(b[1]));
}

// ---------------------------------------------------------------------------
// K1: W [2^20,128] f32 -> Wp [2^19][128] u32, Wp[k2][n] = {W[2k2][n], W[2k2+1][n]}
// ---------------------------------------------------------------------------
__global__ void __launch_bounds__(256) pack_w_kernel(const float* __restrict__ W,
                                                     uint32_t* __restrict__ Wp) {
    size_t idx = (size_t)blockIdx.x * 256 + threadIdx.x;  // uint4 index, 2^24 total
    size_t k2 = idx >> 5;
    int nq = (int)(idx & 31);
    const float4* W4 = reinterpret_cast<const float4*>(W);
    float4 lo = W4[(2 * k2) * 32 + nq];
    float4 hi = W4[(2 * k2 + 1) * 32 + nq];
    uint4 o;
    o.x = pack_h2(lo.x, hi.x);
    o.y = pack_h2(lo.y, hi.y);
    o.z = pack_h2(lo.z, hi.z);
    o.w = pack_h2(lo.w, hi.w);
    reinterpret_cast<uint4*>(Wp)[idx] = o;
}

// ---------------------------------------------------------------------------
// K2: GEMM. grid 296 (mt = bid&3, ks = bid>>2), 256 threads, warps 2(m) x 4(n).
// ---------------------------------------------------------------------------
__global__ void __launch_bounds__(256, 2) gemm_kernel(
    const float* __restrict__ x, const uint32_t* __restrict__ Wp,
    float* __restrict__ partials) {
    extern __shared__ uint32_t smem[];
    uint32_t* const sAh = smem;                     // 2 x [128][20]
    uint32_t* const sBh = smem + 2 * AH_WORDS;      // 4 x [16][136]
    const uint32_t sBh_base = smem_to_u32(sBh);

    const int tid  = threadIdx.x;
    const int wid  = tid >> 5;
    const int lane = tid & 31;
    const int g = lane >> 2;
    const int c = lane & 3;
    const int m_off = (wid >> 2) * 64;   // 2 m-warps
    const int n_off = (wid & 3) * 32;    // 4 n-warps

    const int mt = blockIdx.x & (NUM_MT - 1);
    const int ks = blockIdx.x >> 2;
    const size_t m_base = (size_t)mt * MTILE;
    const int nt = BASE_T + (ks < REM_T ? 1 : 0);
    const long t0 = (long)ks * BASE_T + (ks < REM_T ? ks : REM_T);

    // A: 8 lanes per row (coalesced). row = 32*pass + (tid>>3), 16B chunk q = tid&7.
    const int a_r = tid >> 3;            // 0..31
    const int a_q = tid & 7;             // 0..7
    const float* const a_base = x + (m_base + a_r) * (size_t)K_TOTAL + a_q * 4;

    // B staging: 2 x 16B chunks per thread per stage
    const int b_kr0 = tid >> 5;          // 0..7
    const int b_nq  = tid & 31;

    auto copy_B = [&](int slot, int tile) {
        const size_t k2b = (size_t)(t0 + tile) * (KTILE / 2);
        const uint32_t dst = sBh_base + slot * (BH_SLOT * 4);
        cp_async16(dst + b_kr0 * (BH_PITCH * 4) + b_nq * 16,
                   Wp + ((k2b + b_kr0) << 7) + b_nq * 4);
        cp_async16(dst + (b_kr0 + 8) * (BH_PITCH * 4) + b_nq * 16,
                   Wp + ((k2b + b_kr0 + 8) << 7) + b_nq * 4);
        cp_commit();
    };

    float4 f[4];   // A prefetch registers (4 passes x 16B)
    auto ld_A = [&](int tile) {
        const float* p = a_base + (size_t)(t0 + tile) * KTILE;
#pragma unroll
        for (int ps = 0; ps < 4; ps++)
            f[ps] = *reinterpret_cast<const float4*>(p + (size_t)ps * 32 * K_TOTAL);
    };

    float acc[4][4][4];
#pragma unroll
    for (int mi = 0; mi < 4; mi++)
#pragma unroll
        for (int ni = 0; ni < 4; ni++)
#pragma unroll
            for (int r = 0; r < 4; r++) acc[mi][ni][r] = 0.0f;

    // prologue
    copy_B(0, 0);
    copy_B(1, 1);
    ld_A(0);

    uint32_t* const a_dst0 = sAh + a_r * AH_PITCH + a_q * 2;

    for (int it = 0; it < nt; it++) {
        // pack A(it) from regs -> Ah[it&1]  (STS.64, rows 32*ps + a_r)
        {
            uint32_t* ab = a_dst0 + (it & 1) * AH_WORDS;
#pragma unroll
            for (int ps = 0; ps < 4; ps++) {
                uint2 o;
                o.x = pack_h2(f[ps].x, f[ps].y);
                o.y = pack_h2(f[ps].z, f[ps].w);
                *reinterpret_cast<uint2*>(ab + ps * (32 * AH_PITCH)) = o;
            }
        }
        if (it + 1 < nt) ld_A(it + 1);                 // A prefetch (distance 1)
        if (it + 2 < nt) copy_B((it + 2) & 3, it + 2); // B prefetch (distance 2)
        else cp_commit();                              // uniform group accounting

        cp_wait<2>();      // B(it) landed (outstanding: B(it+1), B(it+2))
        __syncthreads();   // Ah[it&1] + Bh[it&3] visible; old buffers retired

        const uint32_t* Ahp = sAh + (it & 1) * AH_WORDS;
        const uint32_t* Bhp = sBh + (it & 3) * BH_SLOT;
#pragma unroll
        for (int kk = 0; kk < 2; kk++) {
            uint32_t a[4][4], b[4][2];
#pragma unroll
            for (int mi = 0; mi < 4; mi++) {
                const int r0 = m_off + mi * 16 + g;
                const uint32_t* A0 = Ahp + r0 * AH_PITCH + kk * 8;
                const uint32_t* A1 = Ahp + (r0 + 8) * AH_PITCH + kk * 8;
                a[mi][0] = A0[c];
                a[mi][1] = A1[c];
                a[mi][2] = A0[c + 4];
                a[mi][3] = A1[c + 4];
            }
#pragma unroll
            for (int ni = 0; ni < 4; ni++) {
                const int col = n_off + ni * 8 + g;
                b[ni][0] = Bhp[(kk * 8 + c) * BH_PITCH + col];
                b[ni][1] = Bhp[(kk * 8 + c + 4) * BH_PITCH + col];
            }
#pragma unroll
            for (int mi = 0; mi < 4; mi++)
#pragma unroll
                for (int ni = 0; ni < 4; ni++)
                    mma_f16(acc[mi][ni], a[mi], b[ni]);
        }
    }

    // epilogue: 128x128 partial
    float* pt = partials + (size_t)blockIdx.x * (MTILE * N_DIM);
#pragma unroll
    for (int mi = 0; mi < 4; mi++) {
        int r0 = m_off + mi * 16 + g;
#pragma unroll
        for (int ni = 0; ni < 4; ni++) {
            int col = n_off + ni * 8 + 2 * c;
            float2 lo = make_float2(acc[mi][ni][0], acc[mi][ni][1]);
            float2 hi = make_float2(acc[mi][ni][2], acc[mi][ni][3]);
            *reinterpret_cast<float2*>(pt + (size_t)r0 * N_DIM + col) = lo;
            *reinterpret_cast<float2*>(pt + (size_t)(r0 + 8) * N_DIM + col) = hi;
        }
    }
}

// ---------------------------------------------------------------------------
// K3: reduce 74 partials -> out, 4-way MLP
// ---------------------------------------------------------------------------
__global__ void __launch_bounds__(256) reduce_kernel(const float* __restrict__ pt,
                                                     float* __restrict__ out) {
    int t = blockIdx.x * blockDim.x + threadIdx.x;
    int n  = t & (N_DIM - 1);
    int m  = (t >> 7) & (MTILE - 1);
    int mt = t >> 14;
    const size_t off = (size_t)m * N_DIM + n;
    const size_t mtoff = (size_t)mt * (MTILE * N_DIM);
    const size_t stride = (size_t)NUM_MT * (MTILE * N_DIM);
    float s0 = 0.f, s1 = 0.f, s2 = 0.f, s3 = 0.f;
    int ks = 0;
#pragma unroll 4
    for (; ks + 4 <= KSPLITS; ks += 4) {
        s0 += pt[(size_t)ks * stride + mtoff + off];
        s1 += pt[(size_t)(ks + 1) * stride + mtoff + off];
        s2 += pt[(size_t)(ks + 2) * stride + mtoff + off];
        s3 += pt[(size_t)(ks + 3) * stride + mtoff + off];
    }
    for (; ks < KSPLITS; ks++) s0 += pt[(size_t)ks * stride + mtoff + off];
    out[(size_t)(mt * MTILE + m) * N_DIM + n] = (s0 + s1) + (s2 + s3);
}

// ---------------------------------------------------------------------------
extern "C" void kernel_launch(void* const* d_in, const int* in_sizes, int n_in,
                              void* d_out, int out_size) {
    const float* x = (const float*)d_in[0];
    const float* W = (const float*)d_in[1];
    float* out = (float*)d_out;

    uint32_t* Wp = nullptr;
    float* part = nullptr;
    cudaGetSymbolAddress((void**)&Wp, g_Wp);
    cudaGetSymbolAddress((void**)&part, g_part);

    static bool attr_set = false;
    if (!attr_set) {
        cudaFuncSetAttribute(gemm_kernel, cudaFuncAttributeMaxDynamicSharedMemorySize,
                             SMEM_BYTES);
        attr_set = true;
    }

    pack_w_kernel<<<(K_TOTAL / 2) * (N_DIM / 4) / 256, 256>>>(W, Wp);
    gemm_kernel<<<NUM_MT * KSPLITS, 256, SMEM_BYTES>>>(x, Wp, part);
    reduce_kernel<<<(M_TOTAL * N_DIM) / 256, 256>>>(part, out);
}

// round 8
// speedup vs baseline: 3.2183x; 1.0020x over previous
#include <cuda_runtime.h>
#include <cstdint>
#include <cuda_fp16.h>

// ============================================================================
// out[b,n] = sum_k x[b,k] * W[k,n]
//   x: [512, 2^20] f32, W: [2^20, 128] f32, out: [512,128] f32
// R6 design:
//   K1: prepass W -> Wp pair-packed fp16 (u32 = {half k=2j, half k=2j+1})
//   K2: GEMM, CTA 128x128, KTILE=32, split-K 74 (grid 296 = 148 SMs x occ 2).
//       4 warps (2m x 2n), warp tile 64x64 -> halved fragment crossbar traffic.
//       A: coalesced LDG f32 -> reg pack -> STS fp16 (double buffer)
//       B: cp.async fp16 from Wp (4-slot ring); one __syncthreads per stage.
//       mma.sync.m16n8k16.f16 with f32 accumulators.
//   K3: reduce split-K partials
// ============================================================================

static constexpr int M_TOTAL = 512;
static constexpr int N_DIM   = 128;
static constexpr int K_TOTAL = 1 << 20;

static constexpr int MTILE   = 128;
static constexpr int KTILE   = 32;
static constexpr int NUM_MT  = M_TOTAL / MTILE;    // 4
static constexpr int KSPLITS = 74;                 // 296 CTAs = one wave @ occ 2
static constexpr int NTILES_K = K_TOTAL / KTILE;   // 32768
static constexpr int BASE_T  = NTILES_K / KSPLITS; // 442
static constexpr int REM_T   = NTILES_K - BASE_T * KSPLITS; // 60

// smem (u32 units)
static constexpr int AH_PITCH = 20;                     // 16 data u32 + 4 pad
static constexpr int AH_WORDS = MTILE * AH_PITCH;       // 2560 (one buffer)
static constexpr int BH_PITCH = 136;                    // 128 data + 8 pad -> 8c+g banks
static constexpr int BH_SLOT  = (KTILE / 2) * BH_PITCH; // 2176
static constexpr int SMEM_WORDS = 2 * AH_WORDS + 4 * BH_SLOT; // 13824
static constexpr int SMEM_BYTES = SMEM_WORDS * 4;             // 55296

// device scratch
__device__ uint32_t g_Wp[(size_t)(K_TOTAL / 2) * N_DIM];           // 256 MiB
__device__ float g_part[(size_t)KSPLITS * NUM_MT * MTILE * N_DIM]; // 19.4 MiB

// ---------------------------------------------------------------------------
__device__ __forceinline__ uint32_t smem_to_u32(const void* p) {
    uint32_t a;
    asm("{ .reg .u64 t; cvta.to.shared.u64 t, %1; cvt.u32.u64 %0, t; }" : "=r"(a) : "l"(p));
    return a;
}
__device__ __forceinline__ void cp_async16(uint32_t dst, const void* src) {
    asm volatile("cp.async.cg.shared.global [%0], [%1], 16;" :: "r"(dst), "l"(src));
}
__device__ __forceinline__ void cp_commit() {
    asm volatile("cp.async.commit_group;" ::: "memory");
}
template <int N>
__device__ __forceinline__ void cp_wait() {
    asm volatile("cp.async.wait_group %0;" :: "n"(N) : "memory");
}
__device__ __forceinline__ uint32_t pack_h2(float lo, float hi) {
    __half2 h = __floats2half2_rn(lo, hi);   // .x = lo (low 16 bits)
    return *reinterpret_cast<uint32_t*>(&h);
}
__device__ __forceinline__ void mma_f16(float* d, const uint32_t* a, const uint32_t* b) {
    asm volatile(
        "mma.sync.aligned.m16n8k16.row.col.f32.f16.f16.f32 "
        "{%0,%1,%2,%3}, {%4,%5,%6,%7}, {%8,%9}, {%0,%1,%2,%3};"
        : "+f"(d[0]), "+f"(d[1]), "+f"(d[2]), "+f"(d[3])
        : "r"(a[0]), "r"(a[1]), "r"(a[2]), "r"(a[3]), "r"(b[0]), "r"(b[1]));
}

// ---------------------------------------------------------------------------
// K1: W [2^20,128] f32 -> Wp [2^19][128] u32, Wp[k2][n] = {W[2k2][n], W[2k2+1][n]}
// ---------------------------------------------------------------------------
__global__ void __launch_bounds__(256) pack_w_kernel(const float* __restrict__ W,
                                                     uint32_t* __restrict__ Wp) {
    size_t idx = (size_t)blockIdx.x * 256 + threadIdx.x;  // uint4 index, 2^24 total
    size_t k2 = idx >> 5;
    int nq = (int)(idx & 31);
    const float4* W4 = reinterpret_cast<const float4*>(W);
    float4 lo = W4[(2 * k2) * 32 + nq];
    float4 hi = W4[(2 * k2 + 1) * 32 + nq];
    uint4 o;
    o.x = pack_h2(lo.x, hi.x);
    o.y = pack_h2(lo.y, hi.y);
    o.z = pack_h2(lo.z, hi.z);
    o.w = pack_h2(lo.w, hi.w);
    reinterpret_cast<uint4*>(Wp)[idx] = o;
}

// ---------------------------------------------------------------------------
// K2: GEMM. grid 296 (mt = bid&3, ks = bid>>2), 128 threads,
// 4 warps as 2(m) x 2(n), warp tile 64x64.
// ---------------------------------------------------------------------------
__global__ void __launch_bounds__(128, 2) gemm_kernel(
    const float* __restrict__ x, const uint32_t* __restrict__ Wp,
    float* __restrict__ partials) {
    extern __shared__ uint32_t smem[];
    uint32_t* const sAh = smem;                     // 2 x [128][20]
    uint32_t* const sBh = smem + 2 * AH_WORDS;      // 4 x [16][136]
    const uint32_t sBh_base = smem_to_u32(sBh);

    const int tid  = threadIdx.x;
    const int wid  = tid >> 5;
    const int lane = tid & 31;
    const int g = lane >> 2;
    const int c = lane & 3;
    const int m_off = (wid >> 1) * 64;   // 2 m-warps
    const int n_off = (wid & 1) * 64;    // 2 n-warps

    const int mt = blockIdx.x & (NUM_MT - 1);
    const int ks = blockIdx.x >> 2;
    const size_t m_base = (size_t)mt * MTILE;
    const int nt = BASE_T + (ks < REM_T ? 1 : 0);
    const long t0 = (long)ks * BASE_T + (ks < REM_T ? ks : REM_T);

    // A: 8 lanes per row (coalesced). row = 16*pass + (tid>>3), chunk q = tid&7.
    const int a_r = tid >> 3;            // 0..15
    const int a_q = tid & 7;             // 0..7
    const float* const a_base = x + (m_base + a_r) * (size_t)K_TOTAL + a_q * 4;

    // B staging: 4 x 16B chunks per thread per stage (16 rows x 512 B)
    const int b_kr = tid >> 5;           // 0..3
    const int b_nq = tid & 31;

    auto copy_B = [&](int slot, int tile) {
        const size_t k2b = (size_t)(t0 + tile) * (KTILE / 2);
        const uint32_t dst = sBh_base + slot * (BH_SLOT * 4);
#pragma unroll
        for (int i = 0; i < 4; i++) {
            int kr = b_kr + 4 * i;
            cp_async16(dst + kr * (BH_PITCH * 4) + b_nq * 16,
                       Wp + ((k2b + kr) << 7) + b_nq * 4);
        }
        cp_commit();
    };

    float4 f[8];   // A prefetch registers (8 passes x 16B)
    auto ld_A = [&](int tile) {
        const float* p = a_base + (size_t)(t0 + tile) * KTILE;
#pragma unroll
        for (int ps = 0; ps < 8; ps++)
            f[ps] = *reinterpret_cast<const float4*>(p + (size_t)ps * 16 * K_TOTAL);
    };

    float acc[4][8][4];   // 4 m16 x 8 n8 tiles, 4 f32 each = 128 regs
#pragma unroll
    for (int mi = 0; mi < 4; mi++)
#pragma unroll
        for (int ni = 0; ni < 8; ni++)
#pragma unroll
            for (int r = 0; r < 4; r++) acc[mi][ni][r] = 0.0f;

    // prologue
    copy_B(0, 0);
    copy_B(1, 1);
    ld_A(0);

    uint32_t* const a_dst0 = sAh + a_r * AH_PITCH + a_q * 2;

    for (int it = 0; it < nt; it++) {
        // pack A(it) from regs -> Ah[it&1]  (STS.64, rows 16*ps + a_r)
        {
            uint32_t* ab = a_dst0 + (it & 1) * AH_WORDS;
#pragma unroll
            for (int ps = 0; ps < 8; ps++) {
                uint2 o;
                o.x = pack_h2(f[ps].x, f[ps].y);
                o.y = pack_h2(f[ps].z, f[ps].w);
                *reinterpret_cast<uint2*>(ab + ps * (16 * AH_PITCH)) = o;
            }
        }
        if (it + 1 < nt) ld_A(it + 1);                 // A prefetch (distance 1)
        if (it + 2 < nt) copy_B((it + 2) & 3, it + 2); // B prefetch (distance 2)
        else cp_commit();                              // uniform group accounting

        cp_wait<2>();      // B(it) landed (outstanding: B(it+1), B(it+2))
        __syncthreads();   // Ah[it&1] + Bh[it&3] visible; old buffers retired

        const uint32_t* Ahp = sAh + (it & 1) * AH_WORDS;
        const uint32_t* Bhp = sBh + (it & 3) * BH_SLOT;
#pragma unroll
        for (int kk = 0; kk < 2; kk++) {
            uint32_t a[4][4], b[8][2];
#pragma unroll
            for (int mi = 0; mi < 4; mi++) {
                const int r0 = m_off + mi * 16 + g;
                const uint32_t* A0 = Ahp + r0 * AH_PITCH + kk * 8;
                const uint32_t* A1 = Ahp + (r0 + 8) * AH_PITCH + kk * 8;
                a[mi][0] = A0[c];
                a[mi][1] = A1[c];
                a[mi][2] = A0[c + 4];
                a[mi][3] = A1[c + 4];
            }
#pragma unroll
            for (int ni = 0; ni < 8; ni++) {
                const int col = n_off + ni * 8 + g;
                b[ni][0] = Bhp[(kk * 8 + c) * BH_PITCH + col];
                b[ni][1] = Bhp[(kk * 8 + c + 4) * BH_PITCH + col];
            }
#pragma unroll
            for (int mi = 0; mi < 4; mi++)
#pragma unroll
                for (int ni = 0; ni < 8; ni++)
                    mma_f16(acc[mi][ni], a[mi], b[ni]);
        }
    }

    // epilogue: 128x128 partial
    float* pt = partials + (size_t)blockIdx.x * (MTILE * N_DIM);
#pragma unroll
    for (int mi = 0; mi < 4; mi++) {
        int r0 = m_off + mi * 16 + g;
#pragma unroll
        for (int ni = 0; ni < 8; ni++) {
            int col = n_off + ni * 8 + 2 * c;
            float2 lo = make_float2(acc[mi][ni][0], acc[mi][ni][1]);
            float2 hi = make_float2(acc[mi][ni][2], acc[mi][ni][3]);
            *reinterpret_cast<float2*>(pt + (size_t)r0 * N_DIM + col) = lo;
            *reinterpret_cast<float2*>(pt + (size_t)(r0 + 8) * N_DIM + col) = hi;
        }
    }
}

// ---------------------------------------------------------------------------
// K3: reduce 74 partials -> out, 4-way MLP
// ---------------------------------------------------------------------------
__global__ void __launch_bounds__(256) reduce_kernel(const float* __restrict__ pt,
                                                     float* __restrict__ out) {
    int t = blockIdx.x * blockDim.x + threadIdx.x;
    int n  = t & (N_DIM - 1);
    int m  = (t >> 7) & (MTILE - 1);
    int mt = t >> 14;
    const size_t off = (size_t)m * N_DIM + n;
    const size_t mtoff = (size_t)mt * (MTILE * N_DIM);
    const size_t stride = (size_t)NUM_MT * (MTILE * N_DIM);
    float s0 = 0.f, s1 = 0.f, s2 = 0.f, s3 = 0.f;
    int ks = 0;
#pragma unroll 4
    for (; ks + 4 <= KSPLITS; ks += 4) {
        s0 += pt[(size_t)ks * stride + mtoff + off];
        s1 += pt[(size_t)(ks + 1) * stride + mtoff + off];
        s2 += pt[(size_t)(ks + 2) * stride + mtoff + off];
        s3 += pt[(size_t)(ks + 3) * stride + mtoff + off];
    }
    for (; ks < KSPLITS; ks++) s0 += pt[(size_t)ks * stride + mtoff + off];
    out[(size_t)(mt * MTILE + m) * N_DIM + n] = (s0 + s1) + (s2 + s3);
}

// ---------------------------------------------------------------------------
extern "C" void kernel_launch(void* const* d_in, const int* in_sizes, int n_in,
                              void* d_out, int out_size) {
    const float* x = (const float*)d_in[0];
    const float* W = (const float*)d_in[1];
    float* out = (float*)d_out;

    uint32_t* Wp = nullptr;
    float* part = nullptr;
    cudaGetSymbolAddress((void**)&Wp, g_Wp);
    cudaGetSymbolAddress((void**)&part, g_part);

    static bool attr_set = false;
    if (!attr_set) {
        cudaFuncSetAttribute(gemm_kernel, cudaFuncAttributeMaxDynamicSharedMemorySize,
                             SMEM_BYTES);
        attr_set = true;
    }

    pack_w_kernel<<<(K_TOTAL / 2) * (N_DIM / 4) / 256, 256>>>(W, Wp);
    gemm_kernel<<<NUM_MT * KSPLITS, 128, SMEM_BYTES>>>(x, Wp, part);
    reduce_kernel<<<(M_TOTAL * N_DIM) / 256, 256>>>(part, out);
}

// round 9
// speedup vs baseline: 3.8668x; 1.2015x over previous
#include <cuda_runtime.h>
#include <cstdint>
#include <cuda_fp16.h>

// ============================================================================
// out[b,n] = sum_k x[b,k] * W[k,n]
//   x: [512, 2^20] f32, W: [2^20, 128] f32, out: [512,128] f32
// R7 design (fused, no prepass):
//   K1: GEMM, CTA 128x128, KTILE=32, split-K 74 (grid 296 = 148 SMs x occ 2).
//       4 warps (2m x 2n), warp tile 64x64.
//       A: coalesced LDG f32 -> reg -> F2FP pack -> STS fp16 (double buffer)
//       B: coalesced LDG f32 (row-pairs) -> reg -> pair-pack fp16 -> STS
//          (double buffer). W converted on the fly; L2 dedups the 4-way
//          mt redundancy. ONE __syncthreads per stage.
//       mma.sync.m16n8k16.f16 with f32 accumulators. Tensor-pipe-bound
//       (legacy HMMA = 512 MAC/cyc/SM on sm_103).
//   K2: reduce split-K partials
// ============================================================================

static constexpr int M_TOTAL = 512;
static constexpr int N_DIM   = 128;
static constexpr int K_TOTAL = 1 << 20;

static constexpr int MTILE   = 128;
static constexpr int KTILE   = 32;
static constexpr int NUM_MT  = M_TOTAL / MTILE;    // 4
static constexpr int KSPLITS = 74;                 // 296 CTAs = one wave @ occ 2
static constexpr int NTILES_K = K_TOTAL / KTILE;   // 32768
static constexpr int BASE_T  = NTILES_K / KSPLITS; // 442
static constexpr int REM_T   = NTILES_K - BASE_T * KSPLITS; // 60

// smem (u32 units)
static constexpr int AH_PITCH = 20;                     // 16 data u32 + 4 pad
static constexpr int AH_WORDS = MTILE * AH_PITCH;       // 2560 (one buffer)
static constexpr int BH_PITCH = 136;                    // 128 data + 8 pad
static constexpr int BH_SLOT  = (KTILE / 2) * BH_PITCH; // 2176 (one buffer)
static constexpr int SMEM_WORDS = 2 * AH_WORDS + 2 * BH_SLOT; // 9472
static constexpr int SMEM_BYTES = SMEM_WORDS * 4;             // 37888

// split-K partials scratch
__device__ float g_part[(size_t)KSPLITS * NUM_MT * MTILE * N_DIM]; // 19.4 MiB

// ---------------------------------------------------------------------------
__device__ __forceinline__ uint32_t pack_h2(float lo, float hi) {
    __half2 h = __floats2half2_rn(lo, hi);   // .x = lo (low 16 bits)
    return *reinterpret_cast<uint32_t*>(&h);
}
__device__ __forceinline__ void mma_f16(float* d, const uint32_t* a, const uint32_t* b) {
    asm volatile(
        "mma.sync.aligned.m16n8k16.row.col.f32.f16.f16.f32 "
        "{%0,%1,%2,%3}, {%4,%5,%6,%7}, {%8,%9}, {%0,%1,%2,%3};"
        : "+f"(d[0]), "+f"(d[1]), "+f"(d[2]), "+f"(d[3])
        : "r"(a[0]), "r"(a[1]), "r"(a[2]), "r"(a[3]), "r"(b[0]), "r"(b[1]));
}

// ---------------------------------------------------------------------------
// K1: GEMM. grid 296 (mt = bid&3, ks = bid>>2), 128 threads,
// 4 warps as 2(m) x 2(n), warp tile 64x64.
// ---------------------------------------------------------------------------
__global__ void __launch_bounds__(128, 2) gemm_kernel(
    const float* __restrict__ x, const float* __restrict__ W,
    float* __restrict__ partials) {
    extern __shared__ uint32_t smem[];
    uint32_t* const sAh = smem;                     // 2 x [128][20]
    uint32_t* const sBh = smem + 2 * AH_WORDS;      // 2 x [16][136]

    const int tid  = threadIdx.x;
    const int wid  = tid >> 5;
    const int lane = tid & 31;
    const int g = lane >> 2;
    const int c = lane & 3;
    const int m_off = (wid >> 1) * 64;   // 2 m-warps
    const int n_off = (wid & 1) * 64;    // 2 n-warps

    const int mt = blockIdx.x & (NUM_MT - 1);
    const int ks = blockIdx.x >> 2;
    const size_t m_base = (size_t)mt * MTILE;
    const int nt = BASE_T + (ks < REM_T ? 1 : 0);
    const long t0 = (long)ks * BASE_T + (ks < REM_T ? ks : REM_T);

    // A: 8 lanes per row (coalesced). row = 16*pass + (tid>>3), chunk q = tid&7.
    const int a_r = tid >> 3;            // 0..15
    const int a_q = tid & 7;             // 0..7
    const float* const a_base = x + (m_base + a_r) * (size_t)K_TOTAL + a_q * 4;

    // B: thread handles 4 k2-pairs. id = tid + 128*i: k2 = id>>5 (0..15),
    // nq = id&31. Loads rows 2*k2 and 2*k2+1 at float col nq*4 (coalesced 512B).
    const int b_k2 = tid >> 5;           // 0..3 (plus 4*i)
    const int b_nq = tid & 31;
    const float* const b_base = W + (size_t)b_nq * 4;

    float4 f[8];          // A prefetch regs
    float4 blo[4], bhi[4];// B prefetch regs (4 k2-pairs x 2 rows x 16B)

    auto ld_A = [&](int tile) {
        const float* p = a_base + (size_t)(t0 + tile) * KTILE;
#pragma unroll
        for (int ps = 0; ps < 8; ps++)
            f[ps] = *reinterpret_cast<const float4*>(p + (size_t)ps * 16 * K_TOTAL);
    };
    auto ld_B = [&](int tile) {
        const size_t kg = (size_t)(t0 + tile) * KTILE;
        const float* p = b_base + kg * N_DIM;
#pragma unroll
        for (int i = 0; i < 4; i++) {
            const int k2 = b_k2 + 4 * i;
            blo[i] = *reinterpret_cast<const float4*>(p + (size_t)(2 * k2) * N_DIM);
            bhi[i] = *reinterpret_cast<const float4*>(p + (size_t)(2 * k2 + 1) * N_DIM);
        }
    };

    float acc[4][8][4];   // 4 m16 x 8 n8 tiles = 128 regs
#pragma unroll
    for (int mi = 0; mi < 4; mi++)
#pragma unroll
        for (int ni = 0; ni < 8; ni++)
#pragma unroll
            for (int r = 0; r < 4; r++) acc[mi][ni][r] = 0.0f;

    ld_A(0);
    ld_B(0);

    uint32_t* const a_dst0 = sAh + a_r * AH_PITCH + a_q * 2;
    uint32_t* const b_dst0 = sBh + b_k2 * BH_PITCH + b_nq * 4;

    for (int it = 0; it < nt; it++) {
        const int buf = it & 1;
        // pack A(it) -> Ah[buf]  (STS.64, rows 16*ps + a_r)
        {
            uint32_t* ab = a_dst0 + buf * AH_WORDS;
#pragma unroll
            for (int ps = 0; ps < 8; ps++) {
                uint2 o;
                o.x = pack_h2(f[ps].x, f[ps].y);
                o.y = pack_h2(f[ps].z, f[ps].w);
                *reinterpret_cast<uint2*>(ab + ps * (16 * AH_PITCH)) = o;
            }
        }
        // pack B(it) pairs -> Bh[buf]  (STS.128)
        {
            uint32_t* bb = b_dst0 + buf * BH_SLOT;
#pragma unroll
            for (int i = 0; i < 4; i++) {
                uint4 o;
                o.x = pack_h2(blo[i].x, bhi[i].x);
                o.y = pack_h2(blo[i].y, bhi[i].y);
                o.z = pack_h2(blo[i].z, bhi[i].z);
                o.w = pack_h2(blo[i].w, bhi[i].w);
                *reinterpret_cast<uint4*>(bb + i * (4 * BH_PITCH)) = o;
            }
        }
        if (it + 1 < nt) {     // distance-1 register prefetch (hidden by stage)
            ld_A(it + 1);
            ld_B(it + 1);
        }
        __syncthreads();   // Ah[buf]+Bh[buf] complete; prior reads retired

        const uint32_t* Ahp = sAh + buf * AH_WORDS;
        const uint32_t* Bhp = sBh + buf * BH_SLOT;
#pragma unroll
        for (int kk = 0; kk < 2; kk++) {
            uint32_t a[4][4], b[8][2];
#pragma unroll
            for (int mi = 0; mi < 4; mi++) {
                const int r0 = m_off + mi * 16 + g;
                const uint32_t* A0 = Ahp + r0 * AH_PITCH + kk * 8;
                const uint32_t* A1 = Ahp + (r0 + 8) * AH_PITCH + kk * 8;
                a[mi][0] = A0[c];
                a[mi][1] = A1[c];
                a[mi][2] = A0[c + 4];
                a[mi][3] = A1[c + 4];
            }
#pragma unroll
            for (int ni = 0; ni < 8; ni++) {
                const int col = n_off + ni * 8 + g;
                b[ni][0] = Bhp[(kk * 8 + c) * BH_PITCH + col];
                b[ni][1] = Bhp[(kk * 8 + c + 4) * BH_PITCH + col];
            }
#pragma unroll
            for (int mi = 0; mi < 4; mi++)
#pragma unroll
                for (int ni = 0; ni < 8; ni++)
                    mma_f16(acc[mi][ni], a[mi], b[ni]);
        }
    }

    // epilogue: 128x128 partial
    float* pt = partials + (size_t)blockIdx.x * (MTILE * N_DIM);
#pragma unroll
    for (int mi = 0; mi < 4; mi++) {
        int r0 = m_off + mi * 16 + g;
#pragma unroll
        for (int ni = 0; ni < 8; ni++) {
            int col = n_off + ni * 8 + 2 * c;
            float2 lo = make_float2(acc[mi][ni][0], acc[mi][ni][1]);
            float2 hi = make_float2(acc[mi][ni][2], acc[mi][ni][3]);
            *reinterpret_cast<float2*>(pt + (size_t)r0 * N_DIM + col) = lo;
            *reinterpret_cast<float2*>(pt + (size_t)(r0 + 8) * N_DIM + col) = hi;
        }
    }
}

// ---------------------------------------------------------------------------
// K2: reduce 74 partials -> out, 4-way MLP
// ---------------------------------------------------------------------------
__global__ void __launch_bounds__(256) reduce_kernel(const float* __restrict__ pt,
                                                     float* __restrict__ out) {
    int t = blockIdx.x * blockDim.x + threadIdx.x;
    int n  = t & (N_DIM - 1);
    int m  = (t >> 7) & (MTILE - 1);
    int mt = t >> 14;
    const size_t off = (size_t)m * N_DIM + n;
    const size_t mtoff = (size_t)mt * (MTILE * N_DIM);
    const size_t stride = (size_t)NUM_MT * (MTILE * N_DIM);
    float s0 = 0.f, s1 = 0.f, s2 = 0.f, s3 = 0.f;
    int ks = 0;
#pragma unroll 4
    for (; ks + 4 <= KSPLITS; ks += 4) {
        s0 += pt[(size_t)ks * stride + mtoff + off];
        s1 += pt[(size_t)(ks + 1) * stride + mtoff + off];
        s2 += pt[(size_t)(ks + 2) * stride + mtoff + off];
        s3 += pt[(size_t)(ks + 3) * stride + mtoff + off];
    }
    for (; ks < KSPLITS; ks++) s0 += pt[(size_t)ks * stride + mtoff + off];
    out[(size_t)(mt * MTILE + m) * N_DIM + n] = (s0 + s1) + (s2 + s3);
}

// ---------------------------------------------------------------------------
extern "C" void kernel_launch(void* const* d_in, const int* in_sizes, int n_in,
                              void* d_out, int out_size) {
    const float* x = (const float*)d_in[0];
    const float* W = (const float*)d_in[1];
    float* out = (float*)d_out;

    float* part = nullptr;
    cudaGetSymbolAddress((void**)&part, g_part);

    static bool attr_set = false;
    if (!attr_set) {
        cudaFuncSetAttribute(gemm_kernel, cudaFuncAttributeMaxDynamicSharedMemorySize,
                             SMEM_BYTES);
        attr_set = true;
    }

    gemm_kernel<<<NUM_MT * KSPLITS, 128, SMEM_BYTES>>>(x, W, part);
    reduce_kernel<<<(M_TOTAL * N_DIM) / 256, 256>>>(part, out);
}